// round 3
// baseline (speedup 1.0000x reference)
#include <cuda_runtime.h>

// BrockHommes: B=8192 rows, T=4096 strictly-sequential steps.
// 2 rows per thread, packed into f32x2 (aligned register pairs, FFMA2 SASS).
// Per 2-row step the fma-pipe instruction count ~= the old 1-row count, and the
// ~95-cycle dependency chain now produces TWO rows -> ~2x throughput.
// 4096 threads = 128 blocks x 32; one warp per SM.

#define B_CONST 8192
#define T_CONST 4096
#define HALF_B  (B_CONST / 2)

typedef unsigned long long u64;

__device__ __forceinline__ u64 pk2(float lo, float hi) {
    u64 d; asm("mov.b64 %0, {%1,%2};" : "=l"(d) : "f"(lo), "f"(hi)); return d;
}
__device__ __forceinline__ float lo2(u64 d) {
    float a, b; asm("mov.b64 {%0,%1}, %2;" : "=f"(a), "=f"(b) : "l"(d)); return a;
}
__device__ __forceinline__ float hi2(u64 d) {
    float a, b; asm("mov.b64 {%0,%1}, %2;" : "=f"(a), "=f"(b) : "l"(d)); return b;
}
__device__ __forceinline__ u64 fma2(u64 a, u64 b, u64 c) {
    u64 d; asm("fma.rn.f32x2 %0, %1, %2, %3;" : "=l"(d) : "l"(a), "l"(b), "l"(c)); return d;
}
__device__ __forceinline__ u64 mul2(u64 a, u64 b) {
    u64 d; asm("mul.rn.f32x2 %0, %1, %2;" : "=l"(d) : "l"(a), "l"(b)); return d;
}
__device__ __forceinline__ u64 add2(u64 a, u64 b) {
    u64 d; asm("add.rn.f32x2 %0, %1, %2;" : "=l"(d) : "l"(a), "l"(b)); return d;
}
__device__ __forceinline__ float ex2a(float x) {
    float y; asm("ex2.approx.f32 %0, %1;" : "=f"(y) : "f"(x)); return y;
}
__device__ __forceinline__ float rcpa(float x) {
    float y; asm("rcp.approx.f32 %0, %1;" : "=f"(y) : "f"(x)); return y;
}

__global__ void __launch_bounds__(32, 1)
bh_kernel(const float* __restrict__ theta,
          const float* __restrict__ eps,
          float* __restrict__ out)
{
    int t = blockIdx.x * 32 + threadIdx.x;   // 0..4095
    int rA = t;                // row A
    int rB = t + HALF_B;       // row B

    const float* thA = theta + (size_t)rA * 11;
    const float* thB = theta + (size_t)rB * 11;

    // per-row derived constants
    float betaA = thA[0], betaB = thB[0];
    float sigA  = thA[9], sigB  = thB[9];
    float rrA   = thA[10], rrB  = thB[10];
    float RA = 1.0f + rrA,  RB = 1.0f + rrB;
    float iRA = 1.0f / RA,  iRB = 1.0f / RB;       // one-time accurate div
    const float L2E = 1.44269504088896340736f;
    float blA = betaA * L2E, blB = betaB * L2E;

    // packed constants
    u64 g2[4], b2[4], gi2[4], bi2[4];
    #pragma unroll
    for (int k = 0; k < 4; ++k) {
        float gA = thA[1 + k], gB = thB[1 + k];
        float bA = thA[5 + k], bB = thB[5 + k];
        g2[k]  = pk2(gA, gB);
        b2[k]  = pk2(bA, bB);
        gi2[k] = pk2(gA * iRA, gB * iRB);
        bi2[k] = pk2(bA * iRA, bB * iRB);
    }
    u64 bl2   = pk2(blA, blB);
    u64 blnR2 = pk2(-blA * RA, -blB * RB);   // for sL = bl*x1 + (-bl*R)*x2
    u64 nR2   = pk2(-RA, -RB);               // for -R*x2
    u64 sigR2 = pk2(sigA * iRA, sigB * iRB);

    const float4* epA = reinterpret_cast<const float4*>(eps + (size_t)rA * T_CONST);
    const float4* epB = reinterpret_cast<const float4*>(eps + (size_t)rB * T_CONST);
    float4* oA = reinterpret_cast<float4*>(out + (size_t)rA * T_CONST);
    float4* oB = reinterpret_cast<float4*>(out + (size_t)rB * T_CONST);
    const int T4 = T_CONST / 4;

    u64 x1 = 0ull, x2 = 0ull, x3 = 0ull;   // packed (rowA, rowB) state

    // distance-2 prefetch pipeline for eps (both rows)
    float4 bA0 = epA[0], bA1 = epA[1];
    float4 bB0 = epB[0], bB1 = epB[1];

    for (int i = 0; i < T4; ++i) {
        float4 evA = bA0, evB = bB0;
        bA0 = bA1; bB0 = bB1;
        if (i + 2 < T4) { bA1 = epA[i + 2]; bB1 = epB[i + 2]; }

        u64 es[4];
        es[0] = mul2(pk2(evA.x, evB.x), sigR2);
        es[1] = mul2(pk2(evA.y, evB.y), sigR2);
        es[2] = mul2(pk2(evA.z, evB.z), sigR2);
        es[3] = mul2(pk2(evA.w, evB.w), sigR2);

        float xoA[4], xoB[4];

        #pragma unroll
        for (int k = 0; k < 4; ++k) {
            // --- prep from x2/x3 (off the fresh-x1 path; ptxas hoists) ---
            u64 nRx2 = mul2(nR2, x2);                 // -R*x2
            u64 sLa  = mul2(blnR2, x2);               // -bl*R*x2
            u64 bb0 = add2(b2[0], nRx2);
            u64 bb1 = add2(b2[1], nRx2);
            u64 bb2 = add2(b2[2], nRx2);
            u64 bb3 = add2(b2[3], nRx2);
            u64 c0 = fma2(g2[0], x3, bb0);
            u64 c1 = fma2(g2[1], x3, bb1);
            u64 c2 = fma2(g2[2], x3, bb2);
            u64 c3 = fma2(g2[3], x3, bb3);
            // per-row max/min of c (alu pipe, scalar FMNMX)
            float cxA = fmaxf(fmaxf(lo2(c0), lo2(c1)), fmaxf(lo2(c2), lo2(c3)));
            float cnA = fminf(fminf(lo2(c0), lo2(c1)), fminf(lo2(c2), lo2(c3)));
            float cxB = fmaxf(fmaxf(hi2(c0), hi2(c1)), fmaxf(hi2(c2), hi2(c3)));
            float cnB = fminf(fminf(hi2(c0), hi2(c1)), fminf(hi2(c2), hi2(c3)));
            u64 cmax2 = pk2(cxA, cxB);
            u64 cmin2 = pk2(cnA, cnB);

            // --- critical path: depends on fresh x1 ---
            u64 sL = fma2(bl2, x1, sLa);              // bl*(x1 - R*x2)

            u64 Ma = mul2(sL, cmax2);
            u64 Mb = mul2(sL, cmin2);
            // -M = min(-Ma, -Mb)  (FMNMX with neg modifiers, alu pipe)
            float nMA = fminf(-lo2(Ma), -lo2(Mb));
            float nMB = fminf(-hi2(Ma), -hi2(Mb));
            u64 nM2 = pk2(nMA, nMB);

            u64 a0 = fma2(sL, c0, nM2);               // t_k - M <= 0
            u64 a1 = fma2(sL, c1, nM2);
            u64 a2 = fma2(sL, c2, nM2);
            u64 a3 = fma2(sL, c3, nM2);

            u64 p0 = pk2(ex2a(lo2(a0)), ex2a(hi2(a0)));
            u64 p1 = pk2(ex2a(lo2(a1)), ex2a(hi2(a1)));
            u64 p2 = pk2(ex2a(lo2(a2)), ex2a(hi2(a2)));
            u64 p3 = pk2(ex2a(lo2(a3)), ex2a(hi2(a3)));

            u64 m0 = fma2(gi2[0], x1, bi2[0]);        // (g x1 + b)/R
            u64 m1 = fma2(gi2[1], x1, bi2[1]);
            u64 m2 = fma2(gi2[2], x1, bi2[2]);
            u64 m3 = fma2(gi2[3], x1, bi2[3]);

            u64 den = add2(add2(p0, p1), add2(p2, p3));          // in [1,4]
            u64 num = add2(fma2(p1, m1, mul2(p0, m0)),
                           fma2(p3, m3, mul2(p2, m2)));

            u64 rd = pk2(rcpa(lo2(den)), rcpa(hi2(den)));
            u64 xt = fma2(num, rd, es[k]);            // mean/R + eps*sigma/R

            x3 = x2; x2 = x1; x1 = xt;
            xoA[k] = lo2(xt);
            xoB[k] = hi2(xt);
        }

        oA[i] = make_float4(xoA[0], xoA[1], xoA[2], xoA[3]);
        oB[i] = make_float4(xoB[0], xoB[1], xoB[2], xoB[3]);
    }
}

extern "C" void kernel_launch(void* const* d_in, const int* in_sizes, int n_in,
                              void* d_out, int out_size)
{
    const float* theta = (const float*)d_in[0];   // (B, 11) float32
    const float* eps   = (const float*)d_in[1];   // (B, T)  float32
    float*       out   = (float*)d_out;           // (B, T)  float32

    bh_kernel<<<HALF_B / 32, 32>>>(theta, eps, out);
}

// round 4
// speedup vs baseline: 1.1957x; 1.1957x over previous
#include <cuda_runtime.h>

// BrockHommes: B=8192 rows, T=4096 strictly-sequential steps.
//
// Key algebra: softmax is shift-invariant across regimes, and the -R*x2 term
// in the exponent factor (g_k*x3 + b_k - R*x2) is common to all k, so
//   w = softmax_k( sL * d_k ),  d_k = g_k*x3 + b_k,  sL = beta*log2e*(x1-R*x2).
// d_k / dmax / dmin depend only on x3 (two-step-old state) => fully off the
// critical path. Chain: u -> sL -> M -> a_k -> ex2 -> den -> rcp -> xt (~90cyc).
//
// 2 independent rows per thread (scalar), interleaved by ptxas so the two
// ~90-cycle chains hide each other's MUFU/fma bubbles.
// 4096 threads = 128 blocks x 32 = 1 warp per SM.

#define B_CONST 8192
#define T_CONST 4096
#define HALF_B  (B_CONST / 2)

__device__ __forceinline__ float ex2a(float x) {
    float y; asm("ex2.approx.f32 %0, %1;" : "=f"(y) : "f"(x)); return y;
}
__device__ __forceinline__ float rcpa(float x) {
    float y; asm("rcp.approx.f32 %0, %1;" : "=f"(y) : "f"(x)); return y;
}

__global__ void __launch_bounds__(32, 1)
bh_kernel(const float* __restrict__ theta,
          const float* __restrict__ eps,
          float* __restrict__ out)
{
    const int t = blockIdx.x * 32 + threadIdx.x;   // 0..4095
    const int rA = t;
    const int rB = t + HALF_B;

    const float* thA = theta + (size_t)rA * 11;
    const float* thB = theta + (size_t)rB * 11;

    const float L2E = 1.44269504088896340736f;

    // ---- row A constants ----
    const float gA0 = thA[1], gA1 = thA[2], gA2 = thA[3], gA3 = thA[4];
    const float bA0 = thA[5], bA1 = thA[6], bA2 = thA[7], bA3 = thA[8];
    const float RA   = 1.0f + thA[10];
    const float iRA  = 1.0f / RA;
    const float blA  = thA[0] * L2E;
    const float nRA  = -RA;
    const float sgA  = thA[9] * iRA;
    const float giA0 = gA0 * iRA, giA1 = gA1 * iRA, giA2 = gA2 * iRA, giA3 = gA3 * iRA;
    const float biA0 = bA0 * iRA, biA1 = bA1 * iRA, biA2 = bA2 * iRA, biA3 = bA3 * iRA;

    // ---- row B constants ----
    const float gB0 = thB[1], gB1 = thB[2], gB2 = thB[3], gB3 = thB[4];
    const float bB0 = thB[5], bB1 = thB[6], bB2 = thB[7], bB3 = thB[8];
    const float RB   = 1.0f + thB[10];
    const float iRB  = 1.0f / RB;
    const float blB  = thB[0] * L2E;
    const float nRB  = -RB;
    const float sgB  = thB[9] * iRB;
    const float giB0 = gB0 * iRB, giB1 = gB1 * iRB, giB2 = gB2 * iRB, giB3 = gB3 * iRB;
    const float biB0 = bB0 * iRB, biB1 = bB1 * iRB, biB2 = bB2 * iRB, biB3 = bB3 * iRB;

    const float4* epA = reinterpret_cast<const float4*>(eps + (size_t)rA * T_CONST);
    const float4* epB = reinterpret_cast<const float4*>(eps + (size_t)rB * T_CONST);
    float4* oA = reinterpret_cast<float4*>(out + (size_t)rA * T_CONST);
    float4* oB = reinterpret_cast<float4*>(out + (size_t)rB * T_CONST);
    const int T4 = T_CONST / 4;

    // state
    float xA1 = 0.f, xA2 = 0.f, xA3 = 0.f;
    float xB1 = 0.f, xB2 = 0.f, xB3 = 0.f;

    // regime prep (depends only on x3)
    float dA0 = bA0, dA1 = bA1, dA2 = bA2, dA3 = bA3;   // x3 = 0
    float dB0 = bB0, dB1 = bB1, dB2 = bB2, dB3 = bB3;
    float dmxA = fmaxf(fmaxf(dA0, dA1), fmaxf(dA2, dA3));
    float dmnA = fminf(fminf(dA0, dA1), fminf(dA2, dA3));
    float dmxB = fmaxf(fmaxf(dB0, dB1), fmaxf(dB2, dB3));
    float dmnB = fminf(fminf(dB0, dB1), fminf(dB2, dB3));

    // distance-2 prefetch
    float4 fA0 = epA[0], fA1 = epA[1];
    float4 fB0 = epB[0], fB1 = epB[1];

    for (int i = 0; i < T4; ++i) {
        float4 evA = fA0, evB = fB0;
        fA0 = fA1; fB0 = fB1;
        if (i + 2 < T4) { fA1 = epA[i + 2]; fB1 = epB[i + 2]; }

        float esA[4] = {evA.x * sgA, evA.y * sgA, evA.z * sgA, evA.w * sgA};
        float esB[4] = {evB.x * sgB, evB.y * sgB, evB.z * sgB, evB.w * sgB};
        float xoA[4], xoB[4];

        #pragma unroll
        for (int k = 0; k < 4; ++k) {
            // =========== row A step ===========
            float uA  = fmaf(nRA, xA2, xA1);          // x1 - R*x2
            float sLA = blA * uA;

            float MaA = sLA * dmxA;
            float MbA = sLA * dmnA;
            float nMA = fminf(-MaA, -MbA);            // -max(t_k)

            float aA0 = fmaf(sLA, dA0, nMA);
            float aA1 = fmaf(sLA, dA1, nMA);
            float aA2 = fmaf(sLA, dA2, nMA);
            float aA3 = fmaf(sLA, dA3, nMA);

            float pA0 = ex2a(aA0);
            float pA1 = ex2a(aA1);
            float pA2 = ex2a(aA2);
            float pA3 = ex2a(aA3);

            float mA0 = fmaf(giA0, xA1, biA0);
            float mA1 = fmaf(giA1, xA1, biA1);
            float mA2 = fmaf(giA2, xA1, biA2);
            float mA3 = fmaf(giA3, xA1, biA3);

            float denA = (pA0 + pA1) + (pA2 + pA3);   // in [1,4]
            float numA = fmaf(pA1, mA1, pA0 * mA0) + fmaf(pA3, mA3, pA2 * mA2);

            float rdA = rcpa(denA);
            float xtA = fmaf(numA, rdA, esA[k]);

            // =========== row B step ===========
            float uB  = fmaf(nRB, xB2, xB1);
            float sLB = blB * uB;

            float MaB = sLB * dmxB;
            float MbB = sLB * dmnB;
            float nMB = fminf(-MaB, -MbB);

            float aB0 = fmaf(sLB, dB0, nMB);
            float aB1 = fmaf(sLB, dB1, nMB);
            float aB2 = fmaf(sLB, dB2, nMB);
            float aB3 = fmaf(sLB, dB3, nMB);

            float pB0 = ex2a(aB0);
            float pB1 = ex2a(aB1);
            float pB2 = ex2a(aB2);
            float pB3 = ex2a(aB3);

            float mB0 = fmaf(giB0, xB1, biB0);
            float mB1 = fmaf(giB1, xB1, biB1);
            float mB2 = fmaf(giB2, xB1, biB2);
            float mB3 = fmaf(giB3, xB1, biB3);

            float denB = (pB0 + pB1) + (pB2 + pB3);
            float numB = fmaf(pB1, mB1, pB0 * mB0) + fmaf(pB3, mB3, pB2 * mB2);

            float rdB = rcpa(denB);
            float xtB = fmaf(numB, rdB, esB[k]);

            // =========== shift + off-path prep for next step ===========
            xA3 = xA2; xA2 = xA1; xA1 = xtA;
            xB3 = xB2; xB2 = xB1; xB1 = xtB;
            xoA[k] = xtA;
            xoB[k] = xtB;

            // d_k for next step uses new x3 (= old x2, known one step early)
            dA0 = fmaf(gA0, xA3, bA0);
            dA1 = fmaf(gA1, xA3, bA1);
            dA2 = fmaf(gA2, xA3, bA2);
            dA3 = fmaf(gA3, xA3, bA3);
            dmxA = fmaxf(fmaxf(dA0, dA1), fmaxf(dA2, dA3));
            dmnA = fminf(fminf(dA0, dA1), fminf(dA2, dA3));

            dB0 = fmaf(gB0, xB3, bB0);
            dB1 = fmaf(gB1, xB3, bB1);
            dB2 = fmaf(gB2, xB3, bB2);
            dB3 = fmaf(gB3, xB3, bB3);
            dmxB = fmaxf(fmaxf(dB0, dB1), fmaxf(dB2, dB3));
            dmnB = fminf(fminf(dB0, dB1), fminf(dB2, dB3));
        }

        oA[i] = make_float4(xoA[0], xoA[1], xoA[2], xoA[3]);
        oB[i] = make_float4(xoB[0], xoB[1], xoB[2], xoB[3]);
    }
}

extern "C" void kernel_launch(void* const* d_in, const int* in_sizes, int n_in,
                              void* d_out, int out_size)
{
    const float* theta = (const float*)d_in[0];   // (B, 11) float32
    const float* eps   = (const float*)d_in[1];   // (B, T)  float32
    float*       out   = (float*)d_out;           // (B, T)  float32

    bh_kernel<<<HALF_B / 32, 32>>>(theta, eps, out);
}

// round 5
// speedup vs baseline: 1.6168x; 1.3522x over previous
#include <cuda_runtime.h>

// BrockHommes: B=8192 rows, T=4096 strictly-sequential steps. One row per
// thread (warp-per-row is mandatory: wall = T * per-step chain latency).
//
// Exact algebra used:
//  * softmax shift-invariance: w = softmax_k(sL * d_k), d_k = g_k*x3 + b_k
//    (the common -R*x2 term cancels);  sL = beta*log2e*(x1 - R*x2).
//  * branch-free true-max subtraction:
//      a_k = fma(sL, d_k - dmax, fmin(0, sL*(dmax-dmin)))
//    == sL*d_k - max(sL*dmax, sL*dmin) for either sign of sL.
//    d_k/dmax/dmin/e1/spread depend only on x3 -> two steps of slack.
//  * recurrence closed through the reciprocal:
//      sL_next = (bl*num)*rd + pre2,  pre2 = fma(bl, es, -bl*R*x1).
// Chain: sL -> sp -> mt -> a_k -> ex2(rt8) -> den -> rcp -> sL_next (~82cy model).

#define B_CONST 8192
#define T_CONST 4096

__device__ __forceinline__ float ex2a(float x) {
    float y; asm("ex2.approx.f32 %0, %1;" : "=f"(y) : "f"(x)); return y;
}
__device__ __forceinline__ float rcpa(float x) {
    float y; asm("rcp.approx.f32 %0, %1;" : "=f"(y) : "f"(x)); return y;
}

__global__ void __launch_bounds__(32, 1)
bh_kernel(const float* __restrict__ theta,
          const float* __restrict__ eps,
          float* __restrict__ out)
{
    const int b = blockIdx.x * 32 + threadIdx.x;   // 0..8191

    const float* th = theta + (size_t)b * 11;
    const float L2E = 1.44269504088896340736f;

    const float g0 = th[1], g1 = th[2], g2 = th[3], g3 = th[4];
    const float c0 = th[5], c1 = th[6], c2 = th[7], c3 = th[8];
    const float R    = 1.0f + th[10];
    const float iR   = 1.0f / R;                 // one-time accurate div
    const float bl   = th[0] * L2E;              // beta * log2(e)
    const float nblR = -bl * R;                  // for sLpre = -bl*R*x
    const float sg   = th[9] * iR;               // sigma / R
    const float gi0 = g0 * iR, gi1 = g1 * iR, gi2 = g2 * iR, gi3 = g3 * iR;
    const float bi0 = c0 * iR, bi1 = c1 * iR, bi2 = c2 * iR, bi3 = c3 * iR;

    const float4* ep4 = reinterpret_cast<const float4*>(eps + (size_t)b * T_CONST);
    float4*       o4  = reinterpret_cast<float4*>(out + (size_t)b * T_CONST);
    const int T4 = T_CONST / 4;

    // state
    float x1 = 0.f, x2 = 0.f;
    // (x3 never needed explicitly: next step's d-prep reads x2 before shift)

    // carried, for the CURRENT step:
    float sL = 0.f;                              // bl*(x1 - R*x2) = 0 at t=0
    // d-prep from x3 = 0:
    float d0 = c0, d1 = c1, d2 = c2, d3 = c3;
    float dmx = fmaxf(fmaxf(d0, d1), fmaxf(d2, d3));
    float dmn = fminf(fminf(d0, d1), fminf(d2, d3));
    float e10 = d0 - dmx, e11 = d1 - dmx, e12 = d2 - dmx, e13 = d3 - dmx;
    float spread = dmx - dmn;

    // distance-2 prefetch
    float4 f0 = ep4[0];
    float4 f1 = ep4[1];

    for (int i = 0; i < T4; ++i) {
        float4 ev = f0;
        f0 = f1;
        int nidx = i + 2 < T4 ? i + 2 : T4 - 1;
        f1 = ep4[nidx];

        float es[4] = {ev.x * sg, ev.y * sg, ev.z * sg, ev.w * sg};
        float xo[4];

        #pragma unroll
        for (int k = 0; k < 4; ++k) {
            // ---- off-path prep for NEXT step (only needs x1, x2, es[k]) ----
            // next step's x3 = current x2; next x2 = current x1.
            float nd0 = fmaf(g0, x2, c0);
            float nd1 = fmaf(g1, x2, c1);
            float nd2 = fmaf(g2, x2, c2);
            float nd3 = fmaf(g3, x2, c3);
            float ndmx = fmaxf(fmaxf(nd0, nd1), fmaxf(nd2, nd3));
            float ndmn = fminf(fminf(nd0, nd1), fminf(nd2, nd3));
            float ne10 = nd0 - ndmx, ne11 = nd1 - ndmx;
            float ne12 = nd2 - ndmx, ne13 = nd3 - ndmx;
            float nspread = ndmx - ndmn;
            float pre2 = fmaf(bl, es[k], nblR * x1);   // bl*es - bl*R*x1

            // ---- critical path (everything depends on sL) ----
            float sp = sL * spread;
            float mt = fminf(0.0f, sp);

            float a0 = fmaf(sL, e10, mt);
            float a1 = fmaf(sL, e11, mt);
            float a2 = fmaf(sL, e12, mt);
            float a3 = fmaf(sL, e13, mt);

            float p0 = ex2a(a0);
            float p1 = ex2a(a1);
            float p2 = ex2a(a2);
            float p3 = ex2a(a3);

            float m0 = fmaf(gi0, x1, bi0);             // (g*x1 + b)/R
            float m1 = fmaf(gi1, x1, bi1);
            float m2 = fmaf(gi2, x1, bi2);
            float m3 = fmaf(gi3, x1, bi3);

            float den = (p0 + p1) + (p2 + p3);         // in [1,4]
            float num = fmaf(p1, m1, p0 * m0) + fmaf(p3, m3, p2 * m2);

            float rd = rcpa(den);
            float blnum = bl * num;

            float xt     = fmaf(num,   rd, es[k]);     // x_t
            float sLnext = fmaf(blnum, rd, pre2);      // bl*(x_t - R*x1)

            // ---- commit step ----
            x2 = x1; x1 = xt;
            sL = sLnext;
            d0 = nd0; d1 = nd1; d2 = nd2; d3 = nd3;
            e10 = ne10; e11 = ne11; e12 = ne12; e13 = ne13;
            spread = nspread;
            xo[k] = xt;
        }

        o4[i] = make_float4(xo[0], xo[1], xo[2], xo[3]);
    }
}

extern "C" void kernel_launch(void* const* d_in, const int* in_sizes, int n_in,
                              void* d_out, int out_size)
{
    const float* theta = (const float*)d_in[0];   // (B, 11) float32
    const float* eps   = (const float*)d_in[1];   // (B, T)  float32
    float*       out   = (float*)d_out;           // (B, T)  float32

    bh_kernel<<<B_CONST / 32, 32>>>(theta, eps, out);
}

// round 6
// speedup vs baseline: 1.6179x; 1.0007x over previous
#include <cuda_runtime.h>

// BrockHommes: B=8192 rows, T=4096 strictly-sequential steps, one row per
// thread (warp-per-row: wall = T * per-step chain latency; all rows in flight).
//
// Algebra (exact):
//  * softmax shift-invariance: w = softmax_k(sL*d_k), d_k = g_k*x3 + b_k
//    (common -R*x2 term cancels);  sL = beta*log2e*(x1 - R*x2).
//  * true-max subtraction, branch-free:
//      a_k = fma(sL, d_k - dmax, fmin(0, sL*(dmax-dmin)))
//        == sL*d_k - max(sL*dmax, sL*dmin)   for either sign of sL.
//  * recurrence closed through the reciprocal:
//      sL_next = (bl*num)*rd + pre2,  pre2 = fma(bl, es, -bl*R*x1).
//
// This round: hand-unrolled 4-step body with macro-renamed scalars (no arrays,
// no commit-MOVs) + arrival-ordered linear reductions (p's land staggered at
// MUFU rt=8, so linear chains beat balanced trees).

#define B_CONST 8192
#define T_CONST 4096

__device__ __forceinline__ float ex2a(float x){float y;asm("ex2.approx.f32 %0, %1;":"=f"(y):"f"(x));return y;}
__device__ __forceinline__ float rcpa(float x){float y;asm("rcp.approx.f32 %0, %1;":"=f"(y):"f"(x));return y;}

// One step. In: ES = eps_t*sigma/R; X1,X2 = x_{t-1},x_{t-2}; SL carried;
// E0..E3 = d_k - dmax (<=0), SPR = dmax - dmin (d_k built from x_{t-3}).
// Out: XT = x_t; SLN = next sL; F0..F3,NSPR = next step's E/SPR (from X2).
#define BH_STEP(ES, X1, X2, SL, E0,E1,E2,E3, SPR, XT, SLN, F0,F1,F2,F3, NSPR) \
  { \
    /* ---- critical path head ---- */ \
    float sp  = SL * SPR; \
    float mt  = fminf(0.0f, sp); \
    float a0 = fmaf(SL, E0, mt); \
    float a1 = fmaf(SL, E1, mt); \
    float a2 = fmaf(SL, E2, mt); \
    float a3 = fmaf(SL, E3, mt); \
    float p0 = ex2a(a0); \
    float p1 = ex2a(a1); \
    float p2 = ex2a(a2); \
    float p3 = ex2a(a3); \
    /* ---- shadow work (fills MUFU latency) ---- */ \
    float m0 = fmaf(gi0, X1, bi0); \
    float m1 = fmaf(gi1, X1, bi1); \
    float m2 = fmaf(gi2, X1, bi2); \
    float m3 = fmaf(gi3, X1, bi3); \
    float pre2 = fmaf(bl, ES, nblR * X1); \
    float nd0 = fmaf(g0, X2, c0); \
    float nd1 = fmaf(g1, X2, c1); \
    float nd2 = fmaf(g2, X2, c2); \
    float nd3 = fmaf(g3, X2, c3); \
    float nmx = fmaxf(fmaxf(nd0, nd1), fmaxf(nd2, nd3)); \
    float nmn = fminf(fminf(nd0, nd1), fminf(nd2, nd3)); \
    F0 = nd0 - nmx; F1 = nd1 - nmx; F2 = nd2 - nmx; F3 = nd3 - nmx; \
    NSPR = nmx - nmn; \
    /* ---- arrival-ordered reductions ---- */ \
    float den = ((p0 + p1) + p2) + p3;                       /* in [1,4] */ \
    float num = fmaf(p3, m3, fmaf(p2, m2, fmaf(p1, m1, p0 * m0))); \
    float rd = rcpa(den); \
    float blnum = bl * num; \
    XT  = fmaf(num, rd, ES); \
    SLN = fmaf(blnum, rd, pre2); \
  }

__global__ void __launch_bounds__(32, 1)
bh_kernel(const float* __restrict__ theta,
          const float* __restrict__ eps,
          float* __restrict__ out)
{
    const int b = blockIdx.x * 32 + threadIdx.x;   // 0..8191

    const float* th = theta + (size_t)b * 11;
    const float L2E = 1.44269504088896340736f;

    const float g0 = th[1], g1 = th[2], g2 = th[3], g3 = th[4];
    const float c0 = th[5], c1 = th[6], c2 = th[7], c3 = th[8];
    const float R    = 1.0f + th[10];
    const float iR   = 1.0f / R;                  // one-time accurate div
    const float bl   = th[0] * L2E;               // beta * log2(e)
    const float nblR = -bl * R;
    const float sg   = th[9] * iR;                // sigma / R
    const float gi0 = g0 * iR, gi1 = g1 * iR, gi2 = g2 * iR, gi3 = g3 * iR;
    const float bi0 = c0 * iR, bi1 = c1 * iR, bi2 = c2 * iR, bi3 = c3 * iR;

    const float4* ep4 = reinterpret_cast<const float4*>(eps + (size_t)b * T_CONST);
    float4*       o4  = reinterpret_cast<float4*>(out + (size_t)b * T_CONST);
    const int T4 = T_CONST / 4;

    // carried state
    float x1 = 0.f, x2 = 0.f;
    float sL = 0.f;
    // d-prep from x3 = 0: d_k = c_k
    float dmx0 = fmaxf(fmaxf(c0, c1), fmaxf(c2, c3));
    float dmn0 = fminf(fminf(c0, c1), fminf(c2, c3));
    float e0 = c0 - dmx0, e1 = c1 - dmx0, e2 = c2 - dmx0, e3 = c3 - dmx0;
    float spr = dmx0 - dmn0;

    // distance-2 prefetch
    float4 bufA = ep4[0];
    float4 bufB = ep4[1];

    for (int i = 0; i < T4; ++i) {
        float4 ev = bufA;
        bufA = bufB;
        int nidx = (i + 2 < T4) ? (i + 2) : (T4 - 1);
        bufB = ep4[nidx];

        float es0 = ev.x * sg, es1 = ev.y * sg, es2 = ev.z * sg, es3 = ev.w * sg;

        float xt0, xt1, xt2, xt3;
        float sLb, sLc, sLd, sLe;
        float u0, u1, u2, u3, spru;      // E-set after step0
        float v0, v1, v2, v3, sprv;      // after step1
        float w0, w1, w2, w3, sprw;      // after step2

        BH_STEP(es0, x1,  x2,  sL,  e0,e1,e2,e3, spr,  xt0, sLb, u0,u1,u2,u3, spru);
        BH_STEP(es1, xt0, x1,  sLb, u0,u1,u2,u3, spru, xt1, sLc, v0,v1,v2,v3, sprv);
        BH_STEP(es2, xt1, xt0, sLc, v0,v1,v2,v3, sprv, xt2, sLd, w0,w1,w2,w3, sprw);
        BH_STEP(es3, xt2, xt1, sLd, w0,w1,w2,w3, sprw, xt3, sLe, e0,e1,e2,e3, spr);

        x2 = xt3 == xt3 ? xt2 : xt2;   // plain renames (kept simple below)
        x2 = xt2;
        x1 = xt3;
        sL = sLe;

        o4[i] = make_float4(xt0, xt1, xt2, xt3);
    }
}

extern "C" void kernel_launch(void* const* d_in, const int* in_sizes, int n_in,
                              void* d_out, int out_size)
{
    const float* theta = (const float*)d_in[0];   // (B, 11) float32
    const float* eps   = (const float*)d_in[1];   // (B, T)  float32
    float*       out   = (float*)d_out;           // (B, T)  float32

    bh_kernel<<<B_CONST / 32, 32>>>(theta, eps, out);
}

// round 7
// speedup vs baseline: 1.7012x; 1.0515x over previous
#include <cuda_runtime.h>

// BrockHommes: B=8192 rows, T=4096 strictly-sequential steps, one row per
// thread; all 8192 rows in flight (256 warps / 148 SMs). Latency-bound.
//
// Algebra (exact up to fp rounding):
//  * softmax shift-invariance, shifted by regime-0 exponent:
//      w_k = p_k / den,  p_0 = 1,  p_k = 2^(sL*(d_k-d_0)) (k=1..3)
//      d_k = g_k*x3 + b_k,  sL = beta*log2e*(x1 - R*x2)
//    (the common -R*x2 factor term cancels in softmax; shifting by d_0
//     removes one ex2 AND the entire max/min-tree prep).
//  * overflow guard: a_k = fmin(sL*(d_k-d_0), 88) -> den <= 1+3*2^88, finite.
//  * recurrence closed through the reciprocal:
//      sL_next = (bl*num)*rd + pre2,  pre2 = fma(bl, es, -bl*R*x1).
// Chain: sL -> mul -> clamp -> ex2(x3, rt8) -> den(linear) -> rcp -> sL_next.

#define B_CONST 8192
#define T_CONST 4096

__device__ __forceinline__ float ex2a(float x){float y;asm("ex2.approx.f32 %0, %1;":"=f"(y):"f"(x));return y;}
__device__ __forceinline__ float rcpa(float x){float y;asm("rcp.approx.f32 %0, %1;":"=f"(y):"f"(x));return y;}

// One step.
// In:  ES = eps_t*sigma/R; X1,X2 = x_{t-1},x_{t-2}; SL carried;
//      E1..E3 = d_k - d_0 (built from x_{t-3}, two steps of slack).
// Out: XT = x_t; SLN = next sL; F1..F3 = next step's E (built from X2).
#define BH_STEP(ES, X1, X2, SL, E1,E2,E3, XT, SLN, F1,F2,F3) \
  { \
    /* ---- critical path head ---- */ \
    float q1 = SL * E1; \
    float q2 = SL * E2; \
    float q3 = SL * E3; \
    float a1 = fminf(q1, 88.0f); \
    float a2 = fminf(q2, 88.0f); \
    float a3 = fminf(q3, 88.0f); \
    float p1 = ex2a(a1); \
    float p2 = ex2a(a2); \
    float p3 = ex2a(a3); \
    /* ---- shadow work (fills MUFU latency) ---- */ \
    float m0 = fmaf(gi0, X1, bi0); \
    float m1 = fmaf(gi1, X1, bi1); \
    float m2 = fmaf(gi2, X1, bi2); \
    float m3 = fmaf(gi3, X1, bi3); \
    float pre2 = fmaf(bl, ES, nblR * X1); \
    float nd0 = fmaf(g0, X2, c0); \
    float nd1 = fmaf(g1, X2, c1); \
    float nd2 = fmaf(g2, X2, c2); \
    float nd3 = fmaf(g3, X2, c3); \
    F1 = nd1 - nd0; F2 = nd2 - nd0; F3 = nd3 - nd0; \
    /* ---- arrival-ordered linear reductions ---- */ \
    float den = ((1.0f + p1) + p2) + p3; \
    float num = fmaf(p3, m3, fmaf(p2, m2, fmaf(p1, m1, m0))); \
    float rd = rcpa(den); \
    float blnum = bl * num; \
    XT  = fmaf(num, rd, ES); \
    SLN = fmaf(blnum, rd, pre2); \
  }

__global__ void __launch_bounds__(32, 1)
bh_kernel(const float* __restrict__ theta,
          const float* __restrict__ eps,
          float* __restrict__ out)
{
    const int b = blockIdx.x * 32 + threadIdx.x;   // 0..8191

    const float* th = theta + (size_t)b * 11;
    const float L2E = 1.44269504088896340736f;

    const float g0 = th[1], g1 = th[2], g2 = th[3], g3 = th[4];
    const float c0 = th[5], c1 = th[6], c2 = th[7], c3 = th[8];
    const float R    = 1.0f + th[10];
    const float iR   = 1.0f / R;                  // one-time accurate div
    const float bl   = th[0] * L2E;               // beta * log2(e)
    const float nblR = -bl * R;
    const float sg   = th[9] * iR;                // sigma / R
    const float gi0 = g0 * iR, gi1 = g1 * iR, gi2 = g2 * iR, gi3 = g3 * iR;
    const float bi0 = c0 * iR, bi1 = c1 * iR, bi2 = c2 * iR, bi3 = c3 * iR;

    const float4* ep4 = reinterpret_cast<const float4*>(eps + (size_t)b * T_CONST);
    float4*       o4  = reinterpret_cast<float4*>(out + (size_t)b * T_CONST);
    const int T4 = T_CONST / 4;

    // carried state
    float x1 = 0.f, x2 = 0.f;
    float sL = 0.f;
    // E-set for the first step (x3 = 0 -> d_k = c_k)
    float e1 = c1 - c0, e2 = c2 - c0, e3 = c3 - c0;

    // distance-2 prefetch
    float4 bufA = ep4[0];
    float4 bufB = ep4[1];

    for (int i = 0; i < T4; ++i) {
        float4 ev = bufA;
        bufA = bufB;
        int nidx = (i + 2 < T4) ? (i + 2) : (T4 - 1);
        bufB = ep4[nidx];

        float es0 = ev.x * sg, es1 = ev.y * sg, es2 = ev.z * sg, es3 = ev.w * sg;

        float xt0, xt1, xt2, xt3;
        float sLb, sLc, sLd, sLe;
        float u1, u2, u3;     // E-set after step0
        float v1, v2, v3;     // after step1
        float w1, w2, w3;     // after step2

        BH_STEP(es0, x1,  x2,  sL,  e1,e2,e3, xt0, sLb, u1,u2,u3);
        BH_STEP(es1, xt0, x1,  sLb, u1,u2,u3, xt1, sLc, v1,v2,v3);
        BH_STEP(es2, xt1, xt0, sLc, v1,v2,v3, xt2, sLd, w1,w2,w3);
        BH_STEP(es3, xt2, xt1, sLd, w1,w2,w3, xt3, sLe, e1,e2,e3);

        x2 = xt2;
        x1 = xt3;
        sL = sLe;

        o4[i] = make_float4(xt0, xt1, xt2, xt3);
    }
}

extern "C" void kernel_launch(void* const* d_in, const int* in_sizes, int n_in,
                              void* d_out, int out_size)
{
    const float* theta = (const float*)d_in[0];   // (B, 11) float32
    const float* eps   = (const float*)d_in[1];   // (B, T)  float32
    float*       out   = (float*)d_out;           // (B, T)  float32

    bh_kernel<<<B_CONST / 32, 32>>>(theta, eps, out);
}